// round 11
// baseline (speedup 1.0000x reference)
#include <cuda_runtime.h>
#include <cstdint>

#define TT 4096
#define BB 128
#define CC 46
#define LL 43
#define NIT 16384             /* total 32-timestep chunk items = BB * 128 */
#define NBLK 592              /* 4 blocks/SM x 148 SMs: zero wave raggedness */
#define GW (NBLK * 4)         /* total warps = 2368 */
#define NINF (-3.4e38f)
#define LN2F 0.6931471805599453f

// ---------------- scratch (static device globals; no allocation) ----------------
__device__ float4 g_cmats[NIT];
__device__ int    g_cexp[NIT];
__device__ float  g_numpart[NIT];

// ---------------- scaled-probability semiring matrix ----------------
// value = 2^e * P, P 2x2 row-major: x=00, y=01, z=10, w=11, max entry in [1,2).
struct SMat { float4 p; int e; };

// C = A (later) * B (earlier): 8 FFMA + integer exponent renorm (no MUFU).
__device__ __forceinline__ SMat smul(const SMat A, const SMat B) {
    SMat C;
    C.p.x = fmaf(A.p.x, B.p.x, A.p.y * B.p.z);
    C.p.y = fmaf(A.p.x, B.p.y, A.p.y * B.p.w);
    C.p.z = fmaf(A.p.z, B.p.x, A.p.w * B.p.z);
    C.p.w = fmaf(A.p.z, B.p.y, A.p.w * B.p.w);
    float mx = fmaxf(fmaxf(C.p.x, C.p.y), fmaxf(C.p.z, C.p.w));
    int   k  = (__float_as_int(mx) >> 23) & 255;         // biased exponent of mx
    float r  = __int_as_float((254 - k) << 23);          // exact 2^(127-k)
    C.p.x *= r; C.p.y *= r; C.p.z *= r; C.p.w *= r;
    C.e = A.e + B.e + (k - 127);
    return C;
}

__device__ __forceinline__ SMat shfl_down_m(const SMat v, int s, int w) {
    SMat r;
    r.p.x = __shfl_down_sync(0xffffffffu, v.p.x, s, w);
    r.p.y = __shfl_down_sync(0xffffffffu, v.p.y, s, w);
    r.p.z = __shfl_down_sync(0xffffffffu, v.p.z, s, w);
    r.p.w = __shfl_down_sync(0xffffffffu, v.p.w, s, w);
    r.e   = __shfl_down_sync(0xffffffffu, v.e,   s, w);
    return r;
}

__device__ __forceinline__ void cp16(uint32_t dst, const float4* src) {
    asm volatile("cp.async.cg.shared.global [%0], [%1], 16;\n" :: "r"(dst), "l"(src));
}

// warp-local prefetch of one 32-timestep item (368 float4 = 5888 B)
__device__ __forceinline__ void prefetch_item(uint32_t dsm, const float* lp,
                                              int it, int lane) {
    const int b = it >> 7;
    const int c = it & 127;
    const float4* src = (const float4*)(lp + ((size_t)b * TT + c * 32) * CC);
#pragma unroll
    for (int k = 0; k < 12; k++) {
        int i = lane + 32 * k;
        if (i < 368) cp16(dsm + i * 16, src + i);
    }
    asm volatile("cp.async.commit_group;\n");
}

// ---------------- k1: flat warp-scheduled pipelined streaming kernel ----------
// grid NBLK x 128 threads. Warp g (global) processes items g, g+GW, g+2GW, ...
__global__ void __launch_bounds__(128) k1_main(
    const float* __restrict__ lp,
    const float* __restrict__ dp,
    const int* __restrict__ lens,
    const int* __restrict__ labels)
{
    __shared__ float  tiles[2][128 * CC];   // 2 x 23552 B; warp w rows [32w,32w+32)
    __shared__ float2 wab[CC];              // (w0, w1) per column; cols 0,2 zeroed
    __shared__ float  scs[2];               // [0]=exp(s_0I), [1]=exp(s_1I)

    const int tid  = threadIdx.x;
    const int lane = tid & 31;
    const int wid  = tid >> 5;
    const int gw   = blockIdx.x * 4 + wid;  // global warp id

    const uint32_t smA = (uint32_t)__cvta_generic_to_shared(&tiles[0][0]) + wid * 368 * 16;
    const uint32_t smB = (uint32_t)__cvta_generic_to_shared(&tiles[1][0]) + wid * 368 * 16;

    // --- prefetch this warp's first item ---
    prefetch_item(smA, lp, gw, lane);

    // --- warp 0: params (overlaps prefetch latency) ---
    if (wid == 0) {
        float a  = dp[lane];
        float bb = (lane + 32 < CC) ? dp[lane + 32] : NINF;
        float m = fmaxf(a, bb);
#pragma unroll
        for (int o = 16; o; o >>= 1) m = fmaxf(m, __shfl_xor_sync(0xffffffffu, m, o));
        float s = __expf(a - m) + __expf(bb - m);
#pragma unroll
        for (int o = 16; o; o >>= 1) s += __shfl_xor_sync(0xffffffffu, s, o);
        const float lz0 = m + __logf(s);
        float a1 = (lane < LL + 1) ? dp[CC + lane] : NINF;
        float b1 = (lane + 32 < LL + 1) ? dp[CC + lane + 32] : NINF;
        float m1 = fmaxf(a1, b1);
#pragma unroll
        for (int o = 16; o; o >>= 1) m1 = fmaxf(m1, __shfl_xor_sync(0xffffffffu, m1, o));
        float s1 = __expf(a1 - m1) + __expf(b1 - m1);
#pragma unroll
        for (int o = 16; o; o >>= 1) s1 += __shfl_xor_sync(0xffffffffu, s1, o);
        const float lz1 = m1 + __logf(s1);
#pragma unroll
        for (int c = lane; c < CC; c += 32) {
            float w0 = 0.f, w1 = 0.f;
            if (c == 1) w0 = __expf(dp[0] - lz0);          // exp(s_O): folds s_O+lp1 into S0
            if (c >= 3) {
                w0 = __expf(dp[c - 2] - lz0);              // exp(s0_lab)
                w1 = __expf(dp[CC + c - 2] - lz1);         // exp(s1_lab)
            }
            wab[c] = make_float2(w0, w1);
        }
        if (lane == 0) {
            scs[0] = __expf(dp[LL + 1] - lz0);   // exp(s_0I)
            scs[1] = __expf(dp[CC] - lz1);       // exp(s_1I)
        }
    }
    __syncthreads();   // wab/scs visible; no block barriers after this point

    // release the dependent k2 launch as early as possible (PDL)
    cudaTriggerProgrammaticLaunchCompletion();

    const float k0 = scs[0], k1c = scs[1];

    int kIter = 0;
    for (int it = gw; it < NIT; it += GW, kIter++) {
        // prefetch next item into alternate buffer, wait for current
        const int nxt = it + GW;
        if (nxt < NIT) {
            prefetch_item((kIter & 1) ? smA : smB, lp, nxt, lane);
            asm volatile("cp.async.wait_group 1;\n");
        } else {
            asm volatile("cp.async.wait_group 0;\n");
        }
        __syncwarp();   // warp-local buffer ownership

        const int b = it >> 7;
        const int c = it & 127;
        const int t = c * 32 + lane;
        const float* rowp = tiles[kIter & 1] + tid * CC;
        const int  lab   = labels[(size_t)b * TT + t];
        const bool valid = t < lens[b];

        // stream 23 float2: exp directly (log-softmax inputs <= 0: no overflow)
        float S0a = 0.f, S0b = 0.f, S1a = 0.f, S1b = 0.f, e2 = 0.f;
        const float2* r2 = (const float2*)rowp;
#pragma unroll
        for (int i = 0; i < 23; i++) {
            float2 q = r2[i];
            float ex = __expf(q.x);
            float ey = __expf(q.y);
            if (i == 1) e2 = ex;                       // exp(lp[2])
            float2 wA = wab[2 * i];
            float2 wB = wab[2 * i + 1];
            S0a = fmaf(ex, wA.x, S0a); S1a = fmaf(ex, wA.y, S1a);
            S0b = fmaf(ey, wB.x, S0b); S1b = fmaf(ey, wB.y, S1b);
        }
        float tok = valid ? rowp[lab] : 0.f;

        SMat M;
        if (valid) {
            M.p = make_float4(S0a + S0b, S1a + S1b, e2 * k0, e2 * k1c);
        } else {
            M.p = make_float4(1.f, 0.f, 0.f, 1.f);
        }
        M.e = 0;

        // warp-level ordered fold over 32 consecutive timesteps (MUFU-free)
#pragma unroll
        for (int s = 1; s < 32; s <<= 1) {
            SMat o = shfl_down_m(M, s, 32);
            if ((lane & (2 * s - 1)) == 0) M = smul(o, M);
        }
        // token warp sum
#pragma unroll
        for (int o = 16; o; o >>= 1) tok += __shfl_xor_sync(0xffffffffu, tok, o);

        if (lane == 0) {
            g_cmats[it]   = M.p;
            g_cexp[it]    = M.e;
            g_numpart[it] = tok;
        }
    }
}

// ---------------- k2: per-batch fold of 128 chunk items (PDL secondary) -------
// one block, 1024 threads; 8 lanes per batch, each folds 16 consecutive chunks.
__global__ void __launch_bounds__(1024) k2_final(
    const float* __restrict__ dp, float* __restrict__ out)
{
    const int tid  = threadIdx.x;
    const int lane = tid & 31;
    const int wid  = tid >> 5;
    __shared__ float s_fin_sh;
    __shared__ float resv[BB];
    __shared__ float red[4];

    // dp-only prologue: overlaps k1 execution (before grid sync)
    if (wid == 0) {
        float a  = dp[lane];
        float bb = (lane + 32 < CC) ? dp[lane + 32] : NINF;
        float m = fmaxf(a, bb);
#pragma unroll
        for (int o = 16; o; o >>= 1) m = fmaxf(m, __shfl_xor_sync(0xffffffffu, m, o));
        float s = __expf(a - m) + __expf(bb - m);
#pragma unroll
        for (int o = 16; o; o >>= 1) s += __shfl_xor_sync(0xffffffffu, s, o);
        if (lane == 0) s_fin_sh = dp[LL + 2] - (m + __logf(s));
    }

    // wait for k1's gmem results to be visible
    cudaGridDependencySynchronize();

    const int b = tid >> 3;          // 0..127
    const int g = tid & 7;           // 0..7
    const int base = b * 128 + g * 16;

    // serial fold of 16 chunks, time-ascending (later x earlier)
    SMat M;
    M.p = g_cmats[base];
    M.e = g_cexp[base];
    float np = g_numpart[base];
#pragma unroll
    for (int j = 1; j < 16; j++) {
        SMat Nx;
        Nx.p = g_cmats[base + j];
        Nx.e = g_cexp[base + j];
        M = smul(Nx, M);
        np += g_numpart[base + j];
    }

    // width-8 shuffle trees
#pragma unroll
    for (int s = 1; s < 8; s <<= 1) {
        SMat o = shfl_down_m(M, s, 8);
        if ((g & (2 * s - 1)) == 0) M = smul(o, M);
    }
#pragma unroll
    for (int s = 4; s; s >>= 1) np += __shfl_down_sync(0xffffffffu, np, s, 8);

    __syncthreads();   // s_fin_sh visible
    if (g == 0) {
        // alpha0=[1,0]: den = e*ln2 + log(P00) + s_fin
        float den = (float)M.e * LN2F + __logf(M.p.x) + s_fin_sh;
        resv[b] = np - den;
    }
    __syncthreads();

    float vv = (tid < BB) ? resv[tid] : 0.f;
#pragma unroll
    for (int o = 16; o; o >>= 1) vv += __shfl_xor_sync(0xffffffffu, vv, o);
    if (lane == 0 && wid < 4) red[wid] = vv;
    __syncthreads();
    if (tid == 0) out[0] = red[0] + red[1] + red[2] + red[3];
}

// ---------------- launcher ----------------
extern "C" void kernel_launch(void* const* d_in, const int* in_sizes, int n_in,
                              void* d_out, int out_size) {
    const float* lp     = (const float*)d_in[0];
    const float* dp     = (const float*)d_in[1];
    const int*   lens   = (const int*)d_in[2];
    const int*   labels = (const int*)d_in[3];

    k1_main<<<NBLK, 128>>>(lp, dp, lens, labels);

    // PDL launch of k2: overlaps its launch latency with k1 execution
    cudaLaunchConfig_t cfg = {};
    cfg.gridDim  = dim3(1, 1, 1);
    cfg.blockDim = dim3(1024, 1, 1);
    cfg.dynamicSmemBytes = 0;
    cfg.stream = 0;
    cudaLaunchAttribute attrs[1];
    attrs[0].id = cudaLaunchAttributeProgrammaticStreamSerialization;
    attrs[0].val.programmaticStreamSerializationAllowed = 1;
    cfg.attrs = attrs;
    cfg.numAttrs = 1;
    cudaLaunchKernelEx(&cfg, k2_final, dp, (float*)d_out);
}

// round 12
// speedup vs baseline: 1.6267x; 1.6267x over previous
#include <cuda_runtime.h>
#include <cstdint>

#define TT 4096
#define BB 128
#define CC 46
#define LL 43
#define NCH 8                 /* chunks (of 32 timesteps per warp) per block */
#define CHB 8                 /* blocks per batch = TT/(64*NCH) */
#define NINF (-3.4e38f)
#define LN2F 0.6931471805599453f

// ---------------- scratch (static device globals; no allocation) ----------------
__device__ float4 g_cmats[BB * CHB];
__device__ int    g_cexp[BB * CHB];
__device__ float  g_numpart[BB * CHB];

// ---------------- scaled-probability semiring matrix ----------------
// value = 2^e * P, P 2x2 row-major: x=00, y=01, z=10, w=11, max entry in [1,2).
struct SMat { float4 p; int e; };

// C = A (later) * B (earlier): 8 FFMA + integer exponent renorm (no MUFU).
__device__ __forceinline__ SMat smul(const SMat A, const SMat B) {
    SMat C;
    C.p.x = fmaf(A.p.x, B.p.x, A.p.y * B.p.z);
    C.p.y = fmaf(A.p.x, B.p.y, A.p.y * B.p.w);
    C.p.z = fmaf(A.p.z, B.p.x, A.p.w * B.p.z);
    C.p.w = fmaf(A.p.z, B.p.y, A.p.w * B.p.w);
    float mx = fmaxf(fmaxf(C.p.x, C.p.y), fmaxf(C.p.z, C.p.w));
    int   k  = (__float_as_int(mx) >> 23) & 255;         // biased exponent of mx
    float r  = __int_as_float((254 - k) << 23);          // exact 2^(127-k)
    C.p.x *= r; C.p.y *= r; C.p.z *= r; C.p.w *= r;
    C.e = A.e + B.e + (k - 127);
    return C;
}

__device__ __forceinline__ SMat shfl_down_m(const SMat v, int s, int w) {
    SMat r;
    r.p.x = __shfl_down_sync(0xffffffffu, v.p.x, s, w);
    r.p.y = __shfl_down_sync(0xffffffffu, v.p.y, s, w);
    r.p.z = __shfl_down_sync(0xffffffffu, v.p.z, s, w);
    r.p.w = __shfl_down_sync(0xffffffffu, v.p.w, s, w);
    r.e   = __shfl_down_sync(0xffffffffu, v.e,   s, w);
    return r;
}

__device__ __forceinline__ void cp16(uint32_t dst, const float4* src) {
    asm volatile("cp.async.cg.shared.global [%0], [%1], 16;\n" :: "r"(dst), "l"(src));
}

// ---------------- k1: warp-private pipelined streaming kernel ----------------
// grid (CHB, BB), block 64 threads (2 warps). Block covers 512 timesteps;
// warp w owns [t0+256w, t0+256w+256), processed as NCH chunks of 32.
__global__ void __launch_bounds__(64) k1_main(
    const float* __restrict__ lp,
    const float* __restrict__ dp,
    const int* __restrict__ lens,
    const int* __restrict__ labels)
{
    __shared__ float  tiles[2][64 * CC];    // 2 x 11776 B; warp w rows [32w,32w+32)
    __shared__ float2 wab[CC];              // (w0, w1) per column; cols 0,2 zeroed
    __shared__ float  scs[2];               // [0]=exp(s_0I), [1]=exp(s_1I)
    __shared__ float4 warpP[2];
    __shared__ int    warpE[2];
    __shared__ float  warpT[2];

    const int tid  = threadIdx.x;
    const int lane = tid & 31;
    const int wid  = tid >> 5;
    const int b    = blockIdx.y;
    const int t0   = blockIdx.x * (64 * NCH);

    // warp w's 256-timestep segment: offset wid * 256 * 46 / 4 = wid * 2944 float4
    const float4* __restrict__ base4 =
        (const float4*)(lp + ((size_t)b * TT + t0) * CC) + (size_t)wid * 2944;
    const uint32_t smA = (uint32_t)__cvta_generic_to_shared(&tiles[0][0]) + wid * 368 * 16;
    const uint32_t smB = (uint32_t)__cvta_generic_to_shared(&tiles[1][0]) + wid * 368 * 16;

    // --- warp-local prefetch of chunk 0 (368 float4 per warp) ---
#pragma unroll
    for (int k = 0; k < 12; k++) {
        int i = lane + 32 * k;
        if (i < 368) cp16(smA + i * 16, base4 + i);
    }
    asm volatile("cp.async.commit_group;\n");

    // --- warp 0: params (overlaps prefetch latency) ---
    if (wid == 0) {
        float a  = dp[lane];
        float bb = (lane + 32 < CC) ? dp[lane + 32] : NINF;
        float m = fmaxf(a, bb);
#pragma unroll
        for (int o = 16; o; o >>= 1) m = fmaxf(m, __shfl_xor_sync(0xffffffffu, m, o));
        float s = __expf(a - m) + __expf(bb - m);
#pragma unroll
        for (int o = 16; o; o >>= 1) s += __shfl_xor_sync(0xffffffffu, s, o);
        const float lz0 = m + __logf(s);
        float a1 = (lane < LL + 1) ? dp[CC + lane] : NINF;
        float b1 = (lane + 32 < LL + 1) ? dp[CC + lane + 32] : NINF;
        float m1 = fmaxf(a1, b1);
#pragma unroll
        for (int o = 16; o; o >>= 1) m1 = fmaxf(m1, __shfl_xor_sync(0xffffffffu, m1, o));
        float s1 = __expf(a1 - m1) + __expf(b1 - m1);
#pragma unroll
        for (int o = 16; o; o >>= 1) s1 += __shfl_xor_sync(0xffffffffu, s1, o);
        const float lz1 = m1 + __logf(s1);
#pragma unroll
        for (int c = lane; c < CC; c += 32) {
            float w0 = 0.f, w1 = 0.f;
            if (c == 1) w0 = __expf(dp[0] - lz0);          // exp(s_O): folds s_O+lp1 into S0
            if (c >= 3) {
                w0 = __expf(dp[c - 2] - lz0);              // exp(s0_lab)
                w1 = __expf(dp[CC + c - 2] - lz1);         // exp(s1_lab)
            }
            wab[c] = make_float2(w0, w1);
        }
        if (lane == 0) {
            scs[0] = __expf(dp[LL + 1] - lz0);   // exp(s_0I)
            scs[1] = __expf(dp[CC] - lz1);       // exp(s_1I)
        }
    }
    __syncthreads();   // wab/scs visible; no more block barriers until the end

    // release the dependent k2 launch as early as possible (PDL)
    cudaTriggerProgrammaticLaunchCompletion();

    const int len = lens[b];
    const float k0 = scs[0], k1c = scs[1];
    float tok_acc = 0.f;
    SMat run;   // meaningful on lane 0 of each warp

    for (int c = 0; c < NCH; c++) {
        if (c + 1 < NCH) {
            const uint32_t dsm = ((c + 1) & 1) ? smB : smA;
            const float4* src = base4 + (size_t)(c + 1) * 368;
#pragma unroll
            for (int k = 0; k < 12; k++) {
                int i = lane + 32 * k;
                if (i < 368) cp16(dsm + i * 16, src + i);
            }
            asm volatile("cp.async.commit_group;\n");
            asm volatile("cp.async.wait_group 1;\n");
        } else {
            asm volatile("cp.async.wait_group 0;\n");
        }
        __syncwarp();   // warp-local buffer ownership

        const float* rowp = tiles[c & 1] + tid * CC;
        const int t = t0 + wid * 256 + c * 32 + lane;
        const int lab = labels[(size_t)b * TT + t];
        const bool valid = t < len;

        // stream 23 float2: exp directly (log-softmax inputs <= 0: no overflow)
        float S0a = 0.f, S0b = 0.f, S1a = 0.f, S1b = 0.f, e2 = 0.f;
        const float2* r2 = (const float2*)rowp;
#pragma unroll
        for (int i = 0; i < 23; i++) {
            float2 q = r2[i];
            float ex = __expf(q.x);
            float ey = __expf(q.y);
            if (i == 1) e2 = ex;                       // exp(lp[2])
            float2 wA = wab[2 * i];
            float2 wB = wab[2 * i + 1];
            S0a = fmaf(ex, wA.x, S0a); S1a = fmaf(ex, wA.y, S1a);
            S0b = fmaf(ey, wB.x, S0b); S1b = fmaf(ey, wB.y, S1b);
        }
        tok_acc += valid ? rowp[lab] : 0.f;

        SMat M;
        if (valid) {
            M.p = make_float4(S0a + S0b, S1a + S1b, e2 * k0, e2 * k1c);
        } else {
            M.p = make_float4(1.f, 0.f, 0.f, 1.f);
        }
        M.e = 0;

        // warp-level ordered fold over 32 consecutive timesteps (MUFU-free)
#pragma unroll
        for (int s = 1; s < 32; s <<= 1) {
            SMat o = shfl_down_m(M, s, 32);
            if ((lane & (2 * s - 1)) == 0) M = smul(o, M);
        }
        run = (c == 0) ? M : smul(M, run);   // valid on lane 0
    }

    // token warp sum; publish per-warp results
#pragma unroll
    for (int o = 16; o; o >>= 1) tok_acc += __shfl_xor_sync(0xffffffffu, tok_acc, o);
    if (lane == 0) { warpP[wid] = run.p; warpE[wid] = run.e; warpT[wid] = tok_acc; }
    __syncthreads();

    if (tid == 0) {
        SMat A, B2;
        A.p  = warpP[0]; A.e  = warpE[0];
        B2.p = warpP[1]; B2.e = warpE[1];
        A = smul(B2, A);                    // warp 1 (later) x warp 0 (earlier)
        const int slot = b * CHB + blockIdx.x;
        g_cmats[slot]   = A.p;
        g_cexp[slot]    = A.e;
        g_numpart[slot] = warpT[0] + warpT[1];
    }
}

// ---------------- k2: chunk reduce + den + num + global sum (PDL secondary) ----
// one block, 1024 threads; 8 lanes per batch (128 batches x 8 chunk slots).
__global__ void __launch_bounds__(1024) k2_final(
    const float* __restrict__ dp, float* __restrict__ out)
{
    const int tid  = threadIdx.x;
    const int lane = tid & 31;
    const int wid  = tid >> 5;
    __shared__ float s_fin_sh;
    __shared__ float resv[BB];
    __shared__ float red[4];

    // dp-only prologue: overlaps k1 execution (before grid sync)
    if (wid == 0) {
        float a  = dp[lane];
        float bb = (lane + 32 < CC) ? dp[lane + 32] : NINF;
        float m = fmaxf(a, bb);
#pragma unroll
        for (int o = 16; o; o >>= 1) m = fmaxf(m, __shfl_xor_sync(0xffffffffu, m, o));
        float s = __expf(a - m) + __expf(bb - m);
#pragma unroll
        for (int o = 16; o; o >>= 1) s += __shfl_xor_sync(0xffffffffu, s, o);
        if (lane == 0) s_fin_sh = dp[LL + 2] - (m + __logf(s));
    }

    // wait for k1's gmem results to be visible
    cudaGridDependencySynchronize();

    const int b = tid >> 3;          // 0..127
    const int g = tid & 7;           // 0..7
    SMat M;
    M.p = g_cmats[b * CHB + g];
    M.e = g_cexp[b * CHB + g];
    float np = g_numpart[b * CHB + g];

#pragma unroll
    for (int s = 1; s < 8; s <<= 1) {
        SMat o = shfl_down_m(M, s, 8);
        if ((g & (2 * s - 1)) == 0) M = smul(o, M);
    }
#pragma unroll
    for (int s = 4; s; s >>= 1) np += __shfl_down_sync(0xffffffffu, np, s, 8);

    __syncthreads();   // s_fin_sh visible
    if (g == 0) {
        // alpha0=[1,0]: den = e*ln2 + log(P00) + s_fin
        float den = (float)M.e * LN2F + __logf(M.p.x) + s_fin_sh;
        resv[b] = np - den;
    }
    __syncthreads();

    float vv = (tid < BB) ? resv[tid] : 0.f;
#pragma unroll
    for (int o = 16; o; o >>= 1) vv += __shfl_xor_sync(0xffffffffu, vv, o);
    if (lane == 0 && wid < 4) red[wid] = vv;
    __syncthreads();
    if (tid == 0) out[0] = red[0] + red[1] + red[2] + red[3];
}

// ---------------- launcher ----------------
extern "C" void kernel_launch(void* const* d_in, const int* in_sizes, int n_in,
                              void* d_out, int out_size) {
    const float* lp     = (const float*)d_in[0];
    const float* dp     = (const float*)d_in[1];
    const int*   lens   = (const int*)d_in[2];
    const int*   labels = (const int*)d_in[3];

    dim3 grid(CHB, BB);
    k1_main<<<grid, 64>>>(lp, dp, lens, labels);

    // PDL launch of k2: overlaps its launch latency with k1 execution
    cudaLaunchConfig_t cfg = {};
    cfg.gridDim  = dim3(1, 1, 1);
    cfg.blockDim = dim3(1024, 1, 1);
    cfg.dynamicSmemBytes = 0;
    cfg.stream = 0;
    cudaLaunchAttribute attrs[1];
    attrs[0].id = cudaLaunchAttributeProgrammaticStreamSerialization;
    attrs[0].val.programmaticStreamSerializationAllowed = 1;
    cfg.attrs = attrs;
    cfg.numAttrs = 1;
    cudaLaunchKernelEx(&cfg, k2_final, dp, (float*)d_out);
}